// round 3
// baseline (speedup 1.0000x reference)
#include <cuda_runtime.h>
#include <cuda_bf16.h>

// Problem constants: b=1, h=w=64, s=5, H=W=1024, ps=32, q=8
#define GRID_T   64
#define NTILES   (GRID_T * GRID_T)      // 4096
#define NSTROKE  5
#define IMG      1024
#define PLANE    (IMG * IMG)            // 1048576

typedef unsigned long long u64;

// Scratch (allocation-free rule: __device__ globals)
__device__ int    g_cnt[NTILES];
__device__ float4 g_sA[NTILES * NSTROKE];   // (C, S, U0, V0)   [scaled by 25]
__device__ float4 g_sB[NTILES * NSTROKE];   // (W, H, -, -)     [scaled by 25]
__device__ float4 g_sC[NTILES * NSTROKE];   // (cr, cg, cb, -)

__device__ __forceinline__ u64 pk2(float lo, float hi) {
    u64 r; asm("mov.b64 %0,{%1,%2};" : "=l"(r) : "f"(lo), "f"(hi)); return r;
}
__device__ __forceinline__ void upk2(u64 v, float& lo, float& hi) {
    asm("mov.b64 {%0,%1},%2;" : "=f"(lo), "=f"(hi) : "l"(v));
}
__device__ __forceinline__ u64 fma2_(u64 a, u64 b, u64 c) {
    u64 r; asm("fma.rn.f32x2 %0,%1,%2,%3;" : "=l"(r) : "l"(a), "l"(b), "l"(c)); return r;
}
__device__ __forceinline__ u64 add2_(u64 a, u64 b) {
    u64 r; asm("add.rn.f32x2 %0,%1,%2;" : "=l"(r) : "l"(a), "l"(b)); return r;
}
__device__ __forceinline__ u64 mul2_(u64 a, u64 b) {
    u64 r; asm("mul.rn.f32x2 %0,%1,%2;" : "=l"(r) : "l"(a), "l"(b)); return r;
}
__device__ __forceinline__ float tanh_(float x) {
    float r; asm("tanh.approx.f32 %0,%1;" : "=f"(r) : "f"(x)); return r;
}

// ---------------------------------------------------------------------------
// Kernel 1: per-STROKE preprocessing, order-preserving compaction of dec==1.
// sigmoid(50*(hw-|u|)) = 0.5*(1+tanh(25*(hw-|u|))) -> fold 25 into coeffs.
// ---------------------------------------------------------------------------
__global__ void prep_kernel(const float* __restrict__ param,
                            const int*   __restrict__ decision) {
    int n = blockIdx.x * blockDim.x + threadIdx.x;
    if (n >= NTILES * NSTROKE) return;
    int t = n / NSTROKE;
    int i = n - t * NSTROKE;

    int d[NSTROKE];
    #pragma unroll
    for (int j = 0; j < NSTROKE; j++) d[j] = decision[t * NSTROKE + j];
    if (i == 0) {
        int cnt = 0;
        #pragma unroll
        for (int j = 0; j < NSTROKE; j++) cnt += (d[j] != 0);
        g_cnt[t] = cnt;
    }
    if (d[i] == 0) return;
    int pos = 0;
    #pragma unroll
    for (int j = 0; j < NSTROKE; j++) pos += (j < i) && (d[j] != 0);

    const float* q = param + (size_t)n * 12;
    float p[8];
    #pragma unroll
    for (int k = 0; k < 8; k++)
        p[k] = 1.0f / (1.0f + expf(-q[k]));     // jax.nn.sigmoid

    float x0 = p[0], y0 = p[1];
    float W = 12.5f * fmaxf(p[2], 0.01f);       // 25 * (wd/2)
    float H = 12.5f * fmaxf(p[3], 0.01f);
    float th = p[4] * 3.14159265358979323846f;
    float st, ct;
    sincosf(th, &st, &ct);

    float C  = 25.0f * ct, S = 25.0f * st;
    float U0 = -(x0 * C + y0 * S);
    float V0 =  (x0 * S - y0 * C);

    int o = t * NSTROKE + pos;
    g_sA[o] = make_float4(C, S, U0, V0);
    g_sB[o] = make_float4(W, H, 0.f, 0.f);
    g_sC[o] = make_float4(p[5], p[6], p[7], 0.f);
}

// ---------------------------------------------------------------------------
// Kernel 2: block = one 16x16 padded-aligned cell. Flattened, pass-ordered
// entry list in smem with per-pass x-offset folded into U0/V0 and constants
// pre-duplicated for f32x2 math. 128 threads, 2 px/thread (rows ty, ty+8)
// processed as f32x2 SIMD lanes.
// ---------------------------------------------------------------------------
__global__ void __launch_bounds__(128)
render_kernel(const float* __restrict__ canvas,
              float*       __restrict__ out) {
    __shared__ float4 sE[4 * NSTROKE * 5];   // per entry: 5 float4 (dup-packed)
    __shared__ int    sCnt[4];
    __shared__ int    sTileB[4];
    __shared__ float  sOX[4], sOY[4];

    const int a = blockIdx.y;            // padded cell row: Y in [16a, 16a+16)
    const int b = blockIdx.x;
    const int tx  = threadIdx.x;         // 0..15
    const int ty  = threadIdx.y;         // 0..7
    const int tid = ty * 16 + tx;

    // --- stage A: per-pass tile resolution ---
    if (tid < 4) {
        const int PR[4] = {0, 1, 1, 0};
        const int PC[4] = {0, 1, 0, 1};
        int r = (((a - 1) & 1) == PR[tid]) ? (a - 1) : a;
        int c = (((b - 1) & 1) == PC[tid]) ? (b - 1) : b;
        bool valid = ((unsigned)r < 64u) && ((unsigned)c < 64u);
        sTileB[tid] = (r * GRID_T + c) * NSTROKE;
        sCnt[tid]   = valid ? g_cnt[r * GRID_T + c] : 0;
        sOX[tid]    = ((float)(16 * (b - c)) + 0.5f) * 0.03125f;
        sOY[tid]    = ((float)(16 * (a - r)) + 0.5f) * 0.03125f;
    }
    __syncthreads();

    // --- stage B: copy & fold entries (pass-major = blend order) ---
    if (tid < 4 * NSTROKE) {
        int p = tid / NSTROKE, i = tid - p * NSTROKE;
        if (i < sCnt[p]) {
            int base = 0;
            if (p > 0) base += sCnt[0];
            if (p > 1) base += sCnt[1];
            if (p > 2) base += sCnt[2];
            int o = sTileB[p] + i;
            float4 A  = g_sA[o];
            float4 B  = g_sB[o];
            float4 Cc = g_sC[o];
            float ox = sOX[p], oy = sOY[p];
            float U0p = fmaf( ox, A.x, A.z);
            float V0p = fmaf(-ox, A.y, A.w);
            int e = (base + i) * 5;
            sE[e + 0] = make_float4(A.x, A.x, A.y, A.y);   // C2, S2
            sE[e + 1] = make_float4(U0p, U0p, V0p, V0p);   // U2, V2
            sE[e + 2] = make_float4(B.x, B.x, B.y, B.y);   // W2, H2
            sE[e + 3] = make_float4(Cc.x, Cc.x, Cc.y, Cc.y); // CR, CG
            sE[e + 4] = make_float4(Cc.z, Cc.z, oy, oy);   // CB, OY2
        }
    }
    __syncthreads();

    const int tot = sCnt[0] + sCnt[1] + sCnt[2] + sCnt[3];

    // --- two pixels per thread: rows (y0, y0+8), packed as f32x2 lanes ---
    const int x  = 16 * b + tx - 8;      // q = 8
    const int y0 = 16 * a + ty - 8;
    const int y1 = y0 + 8;
    const bool vx = (unsigned)x < (unsigned)IMG;
    const bool v0 = vx && ((unsigned)y0 < (unsigned)IMG);
    const bool v1 = vx && ((unsigned)y1 < (unsigned)IMG);
    const int i0 = y0 * IMG + x;
    const int i1 = y1 * IMG + x;

    float r0 = 0.f, g0 = 0.f, b0 = 0.f, r1 = 0.f, g1 = 0.f, b1 = 0.f;
    if (v0) { r0 = canvas[i0]; g0 = canvas[PLANE + i0]; b0 = canvas[2 * PLANE + i0]; }
    if (v1) { r1 = canvas[i1]; g1 = canvas[PLANE + i1]; b1 = canvas[2 * PLANE + i1]; }

    u64 vR = pk2(r0, r1), vG = pk2(g0, g1), vB = pk2(b0, b1);

    const float txf = (float)tx * 0.03125f;
    const float tyf = (float)ty * 0.03125f;
    const u64 txf2  = pk2(txf, txf);
    const u64 ntxf2 = pk2(-txf, -txf);
    const u64 tyf2  = pk2(tyf, tyf + 0.25f);   // second px is +8 rows = +0.25 tile units
    const u64 HALF2 = pk2(0.5f, 0.5f);
    const u64 N1    = pk2(-1.f, -1.f);

    const ulonglong2* sE2 = (const ulonglong2*)sE;

    for (int e = 0; e < tot; e++) {            // order matters: sequential blend
        ulonglong2 E0 = sE2[e * 5 + 0];        // (C2, S2)
        ulonglong2 E1 = sE2[e * 5 + 1];        // (U2, V2)
        ulonglong2 E2 = sE2[e * 5 + 2];        // (W2, H2)
        ulonglong2 E3 = sE2[e * 5 + 3];        // (CR, CG)
        ulonglong2 E4 = sE2[e * 5 + 4];        // (CB, OY2)

        u64 gy2 = add2_(tyf2, E4.y);
        u64 u2  = fma2_(txf2,  E0.x, fma2_(gy2, E0.y, E1.x));
        u64 v2  = fma2_(ntxf2, E0.y, fma2_(gy2, E0.x, E1.y));

        float ua, ub, va, vb, W, Wd, H, Hd;
        upk2(u2, ua, ub); upk2(v2, va, vb);
        upk2(E2.x, W, Wd); upk2(E2.y, H, Hd);

        float t1a = tanh_(W  - fabsf(ua));
        float t1b = tanh_(Wd - fabsf(ub));
        float t2a = tanh_(H  - fabsf(va));
        float t2b = tanh_(Hd - fabsf(vb));

        u64 h1 = fma2_(pk2(t1a, t1b), HALF2, HALF2);
        u64 h2 = fma2_(pk2(t2a, t2b), HALF2, HALF2);
        u64 al = mul2_(h1, h2);                // alpha for both pixels

        vR = fma2_(al, fma2_(vR, N1, E3.x), vR);   // v = a*(c-v)+v
        vG = fma2_(al, fma2_(vG, N1, E3.y), vG);
        vB = fma2_(al, fma2_(vB, N1, E4.x), vB);
    }

    upk2(vR, r0, r1); upk2(vG, g0, g1); upk2(vB, b0, b1);
    if (v0) { out[i0] = r0; out[PLANE + i0] = g0; out[2 * PLANE + i0] = b0; }
    if (v1) { out[i1] = r1; out[PLANE + i1] = g1; out[2 * PLANE + i1] = b1; }
}

// ---------------------------------------------------------------------------
extern "C" void kernel_launch(void* const* d_in, const int* in_sizes, int n_in,
                              void* d_out, int out_size) {
    const float* param    = (const float*)d_in[0];   // (1,64,64,5,12) f32
    const int*   decision = (const int*)  d_in[1];   // (1,64,64,5)    i32
    const float* canvas   = (const float*)d_in[2];   // (1,3,1024,1024) f32
    float*       out      = (float*)d_out;           // (1,3,1024,1024) f32

    prep_kernel<<<(NTILES * NSTROKE + 255) / 256, 256>>>(param, decision);

    dim3 bs(16, 8);          // 128 threads, 2 px/thread (f32x2 lanes)
    dim3 gs(65, 65);         // padded 1040x1040 in 16x16 cells
    render_kernel<<<gs, bs>>>(canvas, out);
}

// round 4
// speedup vs baseline: 1.1345x; 1.1345x over previous
#include <cuda_runtime.h>
#include <cuda_bf16.h>

// Problem constants: b=1, h=w=64, s=5, H=W=1024, ps=32, q=8
#define GRID_T   64
#define NTILES   (GRID_T * GRID_T)      // 4096
#define NSTROKE  5
#define IMG      1024
#define PLANE    (IMG * IMG)            // 1048576

// Scratch (allocation-free rule: __device__ globals)
__device__ int    g_cnt[NTILES];
__device__ float4 g_sA[NTILES * NSTROKE];   // (C, S, U0, V0)        [scaled by 25]
__device__ float4 g_sB[NTILES * NSTROKE];   // (W, H, dS, dC)        [scaled by 25]
__device__ float4 g_sC[NTILES * NSTROKE];   // (cr, cg, cb, -)

__device__ __forceinline__ float tanh_(float x) {
    float r; asm("tanh.approx.f32 %0,%1;" : "=f"(r) : "f"(x)); return r;
}

// ---------------------------------------------------------------------------
// Kernel 1: per-STROKE preprocessing, order-preserving compaction of dec==1.
// sigmoid(50*(hw-|u|)) = 0.5*(1+tanh(25*(hw-|u|))) -> fold 25 into coeffs.
// dS/dC = row-step (4 px = 0.125 tile units) increments for u/v.
// ---------------------------------------------------------------------------
__global__ void prep_kernel(const float* __restrict__ param,
                            const int*   __restrict__ decision) {
    int n = blockIdx.x * blockDim.x + threadIdx.x;
    if (n >= NTILES * NSTROKE) return;
    int t = n / NSTROKE;
    int i = n - t * NSTROKE;

    int d[NSTROKE];
    #pragma unroll
    for (int j = 0; j < NSTROKE; j++) d[j] = decision[t * NSTROKE + j];
    if (i == 0) {
        int cnt = 0;
        #pragma unroll
        for (int j = 0; j < NSTROKE; j++) cnt += (d[j] != 0);
        g_cnt[t] = cnt;
    }
    if (d[i] == 0) return;
    int pos = 0;
    #pragma unroll
    for (int j = 0; j < NSTROKE; j++) pos += (j < i) && (d[j] != 0);

    const float* q = param + (size_t)n * 12;
    float p[8];
    #pragma unroll
    for (int k = 0; k < 8; k++)
        p[k] = 1.0f / (1.0f + expf(-q[k]));     // jax.nn.sigmoid

    float x0 = p[0], y0 = p[1];
    float W = 12.5f * fmaxf(p[2], 0.01f);       // 25 * (wd/2)
    float H = 12.5f * fmaxf(p[3], 0.01f);
    float th = p[4] * 3.14159265358979323846f;
    float st, ct;
    sincosf(th, &st, &ct);

    float C  = 25.0f * ct, S = 25.0f * st;
    float U0 = -(x0 * C + y0 * S);
    float V0 =  (x0 * S - y0 * C);

    int o = t * NSTROKE + pos;
    g_sA[o] = make_float4(C, S, U0, V0);
    g_sB[o] = make_float4(W, H, 0.125f * S, 0.125f * C);
    g_sC[o] = make_float4(p[5], p[6], p[7], 0.f);
}

// ---------------------------------------------------------------------------
// Kernel 2: block = one 16x16 padded-aligned cell, 64 threads (16x4),
// 4 pixels/thread (rows ty, ty+4, ty+8, ty+12). Flattened pass-ordered entry
// list in smem; pass offsets folded into U0/V0 so the inner loop sees only
// thread-local (gx, gy). u/v advance incrementally across the 4 rows.
// ---------------------------------------------------------------------------
__global__ void __launch_bounds__(64)
render_kernel(const float* __restrict__ canvas,
              float*       __restrict__ out) {
    __shared__ float4 sA[4 * NSTROKE];
    __shared__ float4 sB[4 * NSTROKE];
    __shared__ float4 sC[4 * NSTROKE];
    __shared__ int    sCnt[4];
    __shared__ int    sTileB[4];
    __shared__ float  sOX[4], sOY[4];

    const int a = blockIdx.y;            // padded cell row: Y in [16a, 16a+16)
    const int b = blockIdx.x;
    const int tx  = threadIdx.x;         // 0..15
    const int ty  = threadIdx.y;         // 0..3
    const int tid = ty * 16 + tx;

    // --- stage A: per-pass tile resolution ---
    if (tid < 4) {
        const int PR[4] = {0, 1, 1, 0};
        const int PC[4] = {0, 1, 0, 1};
        int r = (((a - 1) & 1) == PR[tid]) ? (a - 1) : a;
        int c = (((b - 1) & 1) == PC[tid]) ? (b - 1) : b;
        bool valid = ((unsigned)r < 64u) && ((unsigned)c < 64u);
        sTileB[tid] = (r * GRID_T + c) * NSTROKE;
        sCnt[tid]   = valid ? g_cnt[r * GRID_T + c] : 0;
        sOX[tid]    = ((float)(16 * (b - c)) + 0.5f) * 0.03125f;
        sOY[tid]    = ((float)(16 * (a - r)) + 0.5f) * 0.03125f;
    }
    __syncthreads();

    // --- stage B: copy entries in pass-major (= blend) order, folding the
    // per-pass offsets into U0/V0 ---
    if (tid < 4 * NSTROKE) {
        int p = tid / NSTROKE, i = tid - p * NSTROKE;
        if (i < sCnt[p]) {
            int base = 0;
            if (p > 0) base += sCnt[0];
            if (p > 1) base += sCnt[1];
            if (p > 2) base += sCnt[2];
            int o = sTileB[p] + i;
            float4 A  = g_sA[o];
            float ox = sOX[p], oy = sOY[p];
            float U0p = fmaf(ox, A.x, fmaf(oy, A.y, A.z));
            float V0p = fmaf(oy, A.x, fmaf(-ox, A.y, A.w));
            int e = base + i;
            sA[e] = make_float4(A.x, A.y, U0p, V0p);
            sB[e] = g_sB[o];
            sC[e] = g_sC[o];
        }
    }
    __syncthreads();

    const int tot = sCnt[0] + sCnt[1] + sCnt[2] + sCnt[3];

    // --- four pixels per thread: rows y0 + {0,4,8,12} ---
    const int x  = 16 * b + tx - 8;      // q = 8
    const int y0 = 16 * a + ty - 8;
    const bool vx = (unsigned)x < (unsigned)IMG;

    float r[4], g[4], bl[4];
    int   idx[4];
    bool  vv[4];
    #pragma unroll
    for (int k = 0; k < 4; k++) {
        int y = y0 + 4 * k;
        idx[k] = y * IMG + x;
        vv[k]  = vx && ((unsigned)y < (unsigned)IMG);
        r[k] = g[k] = bl[k] = 0.f;
        if (vv[k]) {
            r[k]  = canvas[idx[k]];
            g[k]  = canvas[PLANE + idx[k]];
            bl[k] = canvas[2 * PLANE + idx[k]];
        }
    }

    const float gx = (float)tx * 0.03125f;
    const float gy = (float)ty * 0.03125f;

    for (int e = 0; e < tot; e++) {            // order matters: sequential blend
        float4 A  = sA[e];
        float4 B  = sB[e];
        float4 Cc = sC[e];

        float u = fmaf(gx, A.x, fmaf(gy, A.y, A.z));
        float v = fmaf(gy, A.x, fmaf(-gx, A.y, A.w));

        #pragma unroll
        for (int k = 0; k < 4; k++) {
            float t1 = tanh_(B.x - fabsf(u));
            float t2 = tanh_(B.y - fabsf(v));
            float al = fmaf(t1, 0.5f, 0.5f) * fmaf(t2, 0.5f, 0.5f);
            r[k]  = fmaf(al, Cc.x - r[k],  r[k]);
            g[k]  = fmaf(al, Cc.y - g[k],  g[k]);
            bl[k] = fmaf(al, Cc.z - bl[k], bl[k]);
            u += B.z;                           // +4 rows: du = 0.125*S
            v += B.w;                           //          dv = 0.125*C
        }
    }

    #pragma unroll
    for (int k = 0; k < 4; k++) {
        if (vv[k]) {
            out[idx[k]]             = r[k];
            out[PLANE + idx[k]]     = g[k];
            out[2 * PLANE + idx[k]] = bl[k];
        }
    }
}

// ---------------------------------------------------------------------------
extern "C" void kernel_launch(void* const* d_in, const int* in_sizes, int n_in,
                              void* d_out, int out_size) {
    const float* param    = (const float*)d_in[0];   // (1,64,64,5,12) f32
    const int*   decision = (const int*)  d_in[1];   // (1,64,64,5)    i32
    const float* canvas   = (const float*)d_in[2];   // (1,3,1024,1024) f32
    float*       out      = (float*)d_out;           // (1,3,1024,1024) f32

    prep_kernel<<<(NTILES * NSTROKE + 255) / 256, 256>>>(param, decision);

    dim3 bs(16, 4);          // 64 threads, 4 px/thread
    dim3 gs(65, 65);         // padded 1040x1040 in 16x16 cells
    render_kernel<<<gs, bs>>>(canvas, out);
}